// round 1
// baseline (speedup 1.0000x reference)
#include <cuda_runtime.h>
#include <math.h>

#define B_   4
#define L_   4096
#define D_   1024
#define H_   16
#define DK_  64
#define BH_  (B_ * H_)
#define TOPK 8
#define M_   (B_ * L_)   // 16384

// ---------------- scratch (device globals; no runtime allocation) ----------
__device__ float g_Qp[M_ * D_];
__device__ float g_Kp[M_ * D_];
__device__ float g_Vp[M_ * D_];
__device__ float g_pre[M_ * D_];
__device__ float g_qm[BH_ * L_];
__device__ float g_km[BH_ * L_];
__device__ float g_corr[BH_ * L_];
__device__ float g_w[BH_ * TOPK];
__device__ int   g_delays[BH_ * TOPK];

// ---------------- GEMM: C[M,N] = A[M,K] @ W[K,N] + bias[N] -----------------
// fp32, 128x128 block tile, BK=8, 256 threads, 8x8 micro-tile
#define BM 128
#define BN 128
#define BK 8
#define TM 8
#define TN 8

__global__ __launch_bounds__(256) void sgemm_bias_kernel(
    const float* __restrict__ A, const float* __restrict__ W,
    const float* __restrict__ bias, float* __restrict__ C,
    int M, int N, int K)
{
    __shared__ float As[BK][BM];
    __shared__ float Bs[BK][BN];

    const int tid = threadIdx.x;
    const int bx = blockIdx.x;   // N tile
    const int by = blockIdx.y;   // M tile
    const int tx = tid & 15;     // 0..15
    const int ty = tid >> 4;     // 0..15

    // A tile load: 128 rows x 8 cols; each thread one float4
    const int a_row = tid >> 1;          // 0..127
    const int a_col = (tid & 1) << 2;    // 0 or 4
    // B tile load: 8 rows x 128 cols; each thread one float4
    const int b_row = tid >> 5;          // 0..7
    const int b_col = (tid & 31) << 2;   // 0..124

    const float* Aptr = A + (by * BM + a_row) * K + a_col;
    const float* Wptr = W + b_row * N + bx * BN + b_col;

    float acc[TM][TN];
    #pragma unroll
    for (int i = 0; i < TM; i++)
        #pragma unroll
        for (int j = 0; j < TN; j++) acc[i][j] = 0.0f;

    for (int k0 = 0; k0 < K; k0 += BK) {
        float4 av = *(const float4*)(Aptr + k0);
        float4 bv = *(const float4*)(Wptr + k0 * N);
        As[a_col + 0][a_row] = av.x;
        As[a_col + 1][a_row] = av.y;
        As[a_col + 2][a_row] = av.z;
        As[a_col + 3][a_row] = av.w;
        *(float4*)&Bs[b_row][b_col] = bv;
        __syncthreads();

        #pragma unroll
        for (int kk = 0; kk < BK; kk++) {
            float ar[TM], br[TN];
            *(float4*)&ar[0] = *(const float4*)&As[kk][ty * TM];
            *(float4*)&ar[4] = *(const float4*)&As[kk][ty * TM + 4];
            *(float4*)&br[0] = *(const float4*)&Bs[kk][tx * TN];
            *(float4*)&br[4] = *(const float4*)&Bs[kk][tx * TN + 4];
            #pragma unroll
            for (int i = 0; i < TM; i++)
                #pragma unroll
                for (int j = 0; j < TN; j++)
                    acc[i][j] += ar[i] * br[j];
        }
        __syncthreads();
    }

    const int row0 = by * BM + ty * TM;
    const int col0 = bx * BN + tx * TN;
    float bvals[TN];
    *(float4*)&bvals[0] = *(const float4*)&bias[col0];
    *(float4*)&bvals[4] = *(const float4*)&bias[col0 + 4];

    #pragma unroll
    for (int i = 0; i < TM; i++) {
        float4 o0 = make_float4(acc[i][0] + bvals[0], acc[i][1] + bvals[1],
                                acc[i][2] + bvals[2], acc[i][3] + bvals[3]);
        float4 o1 = make_float4(acc[i][4] + bvals[4], acc[i][5] + bvals[5],
                                acc[i][6] + bvals[6], acc[i][7] + bvals[7]);
        *(float4*)&C[(row0 + i) * N + col0]     = o0;
        *(float4*)&C[(row0 + i) * N + col0 + 4] = o1;
    }
}

// ---------------- per-head means: qm/km[bh][l] = mean over DK channels ------
__global__ __launch_bounds__(256) void means_kernel(
    const float* __restrict__ Qp, const float* __restrict__ Kp,
    float* __restrict__ qm, float* __restrict__ km)
{
    int warp = (blockIdx.x * blockDim.x + threadIdx.x) >> 5;
    int lane = threadIdx.x & 31;
    if (warp >= BH_ * L_) return;
    int bh = warp >> 12;       // / L_
    int l  = warp & (L_ - 1);
    int b  = bh >> 4;          // / H_
    int h  = bh & (H_ - 1);
    const float* qp = Qp + (b * L_ + l) * D_ + h * DK_ + lane * 2;
    const float* kp = Kp + (b * L_ + l) * D_ + h * DK_ + lane * 2;
    float2 q2 = *(const float2*)qp;
    float2 k2 = *(const float2*)kp;
    float qs = q2.x + q2.y;
    float ks = k2.x + k2.y;
    #pragma unroll
    for (int o = 16; o > 0; o >>= 1) {
        qs += __shfl_xor_sync(0xFFFFFFFFu, qs, o);
        ks += __shfl_xor_sync(0xFFFFFFFFu, ks, o);
    }
    if (lane == 0) {
        qm[warp] = qs * (1.0f / DK_);
        km[warp] = ks * (1.0f / DK_);
    }
}

// ---------------- circular cross-correlation ------------------------------
// corr[bh][n] = sum_m qm[bh][m] * km[bh][(m-n) mod L]
// grid (BH_, 2): each block computes 2048 n-values; 256 threads x 8 accums.
// k duplicated into a 6144-wide shared window so the inner loop has no mod.
__global__ __launch_bounds__(256) void corr_kernel(
    const float* __restrict__ qm, const float* __restrict__ km,
    float* __restrict__ corr)
{
    __shared__ float sq[L_];
    __shared__ float sk[6144];

    const int bh = blockIdx.x;
    const int chunk = blockIdx.y;          // 0 or 1
    const int wb = (1 - chunk) * 2048;     // window base into k2

    const float* q = qm + bh * L_;
    const float* k = km + bh * L_;

    for (int i = threadIdx.x; i < L_; i += 256) sq[i] = q[i];
    for (int i = threadIdx.x; i < 6144; i += 256) sk[i] = k[(i + wb) & (L_ - 1)];
    __syncthreads();

    const int t = threadIdx.x;
    float acc[8];
    #pragma unroll
    for (int j = 0; j < 8; j++) acc[j] = 0.0f;

    const float* kp = sk + 2048 - t;  // kp[m - 256*j] == km[(m - n_j) mod L]
    #pragma unroll 4
    for (int m = 0; m < L_; m++) {
        float qv = sq[m];
        #pragma unroll
        for (int j = 0; j < 8; j++)
            acc[j] += qv * kp[m - 256 * j];
    }

    #pragma unroll
    for (int j = 0; j < 8; j++)
        corr[bh * L_ + chunk * 2048 + t + 256 * j] = acc[j];
}

// ---------------- top-8 + softmax -----------------------------------------
__global__ __launch_bounds__(256) void top8_kernel(
    const float* __restrict__ corr, float* __restrict__ w, int* __restrict__ delays)
{
    __shared__ float sc[L_];
    __shared__ float svals[256];
    __shared__ int   sidx[256];
    __shared__ float topv[TOPK];
    __shared__ int   topi[TOPK];

    const int bh = blockIdx.x;
    for (int i = threadIdx.x; i < L_; i += 256) sc[i] = corr[bh * L_ + i];
    __syncthreads();

    for (int r = 0; r < TOPK; r++) {
        float best = -INFINITY; int bi = 0;
        for (int i = threadIdx.x; i < L_; i += 256) {
            float v = sc[i];
            if (v > best) { best = v; bi = i; }
        }
        svals[threadIdx.x] = best;
        sidx[threadIdx.x] = bi;
        __syncthreads();
        for (int s = 128; s > 0; s >>= 1) {
            if (threadIdx.x < s) {
                float v2 = svals[threadIdx.x + s];
                int   i2 = sidx[threadIdx.x + s];
                float v1 = svals[threadIdx.x];
                int   i1 = sidx[threadIdx.x];
                if (v2 > v1 || (v2 == v1 && i2 < i1)) {
                    svals[threadIdx.x] = v2;
                    sidx[threadIdx.x] = i2;
                }
            }
            __syncthreads();
        }
        if (threadIdx.x == 0) {
            topv[r] = svals[0];
            topi[r] = sidx[0];
            sc[sidx[0]] = -INFINITY;
        }
        __syncthreads();
    }

    if (threadIdx.x == 0) {
        float mx = topv[0];      // sorted descending
        float e[TOPK], s = 0.0f;
        #pragma unroll
        for (int r = 0; r < TOPK; r++) { e[r] = expf(topv[r] - mx); s += e[r]; }
        float inv = 1.0f / s;
        #pragma unroll
        for (int r = 0; r < TOPK; r++) {
            w[bh * TOPK + r] = e[r] * inv;
            delays[bh * TOPK + r] = topi[r];
        }
    }
}

// ---------------- weighted circular-roll aggregation ----------------------
// pre[b][l][h*64+c] = sum_r w[bh][r] * Vp[b][(l - delay[bh][r]) mod L][h*64+c]
__global__ __launch_bounds__(256) void gather_kernel(
    const float* __restrict__ Vp, const float* __restrict__ w,
    const int* __restrict__ delays, float* __restrict__ out)
{
    unsigned gid = blockIdx.x * blockDim.x + threadIdx.x;  // one float4 each
    int d4 = gid & 255;                 // D_/4 = 256
    int l  = (gid >> 8) & (L_ - 1);
    int b  = gid >> 20;                 // / (256*4096)
    int h  = d4 >> 4;                   // DK_/4 = 16 float4 per head
    int bh = b * H_ + h;

    float4 a = make_float4(0.f, 0.f, 0.f, 0.f);
    #pragma unroll
    for (int r = 0; r < TOPK; r++) {
        float wr = __ldg(&w[bh * TOPK + r]);
        int   dl = __ldg(&delays[bh * TOPK + r]);
        int   lm = (l - dl) & (L_ - 1);
        const float4 v = *(const float4*)(Vp + (b * L_ + lm) * D_ + d4 * 4);
        a.x += wr * v.x; a.y += wr * v.y; a.z += wr * v.z; a.w += wr * v.w;
    }
    *(float4*)(out + (size_t)gid * 4) = a;
}

// ---------------- launch ---------------------------------------------------
extern "C" void kernel_launch(void* const* d_in, const int* in_sizes, int n_in,
                              void* d_out, int out_size)
{
    const float* queries = (const float*)d_in[0];
    const float* keys    = (const float*)d_in[1];
    const float* values  = (const float*)d_in[2];
    const float* Wq = (const float*)d_in[3];
    const float* bq = (const float*)d_in[4];
    const float* Wk = (const float*)d_in[5];
    const float* bk = (const float*)d_in[6];
    const float* Wv = (const float*)d_in[7];
    const float* bv = (const float*)d_in[8];
    const float* Wo = (const float*)d_in[9];
    const float* bo = (const float*)d_in[10];
    float* out = (float*)d_out;

    float *Qp, *Kp, *Vp, *pre, *qm, *km, *corr, *w;
    int* delays;
    cudaGetSymbolAddress((void**)&Qp, g_Qp);
    cudaGetSymbolAddress((void**)&Kp, g_Kp);
    cudaGetSymbolAddress((void**)&Vp, g_Vp);
    cudaGetSymbolAddress((void**)&pre, g_pre);
    cudaGetSymbolAddress((void**)&qm, g_qm);
    cudaGetSymbolAddress((void**)&km, g_km);
    cudaGetSymbolAddress((void**)&corr, g_corr);
    cudaGetSymbolAddress((void**)&w, g_w);
    cudaGetSymbolAddress((void**)&delays, g_delays);

    dim3 gemm_grid(D_ / BN, M_ / BM);   // (8, 128)

    sgemm_bias_kernel<<<gemm_grid, 256>>>(queries, Wq, bq, Qp, M_, D_, D_);
    sgemm_bias_kernel<<<gemm_grid, 256>>>(keys,    Wk, bk, Kp, M_, D_, D_);
    sgemm_bias_kernel<<<gemm_grid, 256>>>(values,  Wv, bv, Vp, M_, D_, D_);

    means_kernel<<<(BH_ * L_ * 32) / 256, 256>>>(Qp, Kp, qm, km);

    dim3 corr_grid(BH_, 2);
    corr_kernel<<<corr_grid, 256>>>(qm, km, corr);

    top8_kernel<<<BH_, 256>>>(corr, w, delays);

    gather_kernel<<<(M_ * D_ / 4) / 256, 256>>>(Vp, w, delays, pre);

    sgemm_bias_kernel<<<gemm_grid, 256>>>(pre, Wo, bo, out, M_, D_, D_);
}

// round 3
// speedup vs baseline: 3.2974x; 3.2974x over previous
#include <cuda_runtime.h>
#include <cuda_bf16.h>
#include <math.h>
#include <stdint.h>

#define B_   4
#define L_   4096
#define D_   1024
#define H_   16
#define DK_  64
#define BH_  (B_ * H_)
#define TOPK 8
#define M_   (B_ * L_)   // 16384

// ---------------- scratch (device globals; no runtime allocation) ----------
__device__ float g_Qp[M_ * D_];
__device__ float g_Kp[M_ * D_];
__device__ float g_Vp[M_ * D_];
__device__ float g_pre[M_ * D_];
__device__ float g_qm[BH_ * L_];
__device__ float g_km[BH_ * L_];
__device__ float g_corr[BH_ * L_];
__device__ float g_w[BH_ * TOPK];
__device__ int   g_delays[BH_ * TOPK];

// ---------------- tf32 mma GEMM -------------------------------------------
// C[M,1024] = A[M,1024] @ W[1024,1024] + bias
// block tile 128x128x32, 256 threads (8 warps, 4x2), warp tile 32x64
// 3-stage cp.async pipeline, XOR-swizzled smem (conflict-free fragment LDS)

#define A_ST_F 4096            // 128 rows x 32 k  (floats)
#define B_ST_F 4096            // 32 k x 128 n
#define STAGE_F 8192
#define STAGE_BYTES (STAGE_F * 4)
#define GEMM_SMEM (3 * STAGE_BYTES)   // 96 KB

__device__ __forceinline__ uint32_t smem_u32(const void* p) {
    uint32_t a;
    asm("{ .reg .u64 t; cvta.to.shared.u64 t, %1; cvt.u32.u64 %0, t; }"
        : "=r"(a) : "l"(p));
    return a;
}
__device__ __forceinline__ void cp16(uint32_t dst, const void* src) {
    asm volatile("cp.async.cg.shared.global [%0], [%1], 16;"
                 :: "r"(dst), "l"(src));
}
__device__ __forceinline__ uint32_t f2tf32(float f) {
    uint32_t u;
    asm("cvt.rna.tf32.f32 %0, %1;" : "=r"(u) : "f"(f));
    return u;
}
__device__ __forceinline__ void mma_tf32(float* d, const uint32_t* a, const uint32_t* b) {
    asm volatile(
        "mma.sync.aligned.m16n8k8.row.col.f32.tf32.tf32.f32 "
        "{%0,%1,%2,%3}, {%4,%5,%6,%7}, {%8,%9}, {%0,%1,%2,%3};"
        : "+f"(d[0]), "+f"(d[1]), "+f"(d[2]), "+f"(d[3])
        : "r"(a[0]), "r"(a[1]), "r"(a[2]), "r"(a[3]), "r"(b[0]), "r"(b[1]));
}

__global__ __launch_bounds__(256) void gemm_tf32_kernel(
    const float* __restrict__ A, const float* __restrict__ W,
    const float* __restrict__ bias, float* __restrict__ C)
{
    extern __shared__ float sm[];
    const uint32_t su = smem_u32(sm);
    const int tid = threadIdx.x;
    const int bn = blockIdx.x;           // 0..7
    const int bm = blockIdx.y;           // 0..127
    const int wid = tid >> 5, lane = tid & 31;
    const int wm = wid >> 1, wn = wid & 1;
    const int qr = lane >> 2, qc = lane & 3;

    // global load bases
    const float* Ab = A + (size_t)(bm * 128 + (tid >> 3)) * 1024 + (tid & 7) * 4;
    const float* Wb = W + (size_t)(tid >> 5) * 1024 + bn * 128 + (tid & 31) * 4;

    // smem byte offsets (per pass), swizzled
    uint32_t saoff[4], sboff[4];
    #pragma unroll
    for (int p = 0; p < 4; p++) {
        int row = (tid >> 3) + p * 32;
        saoff[p] = (row * 32 + (((tid & 7) ^ (row & 7)) << 2)) * 4;
        int k = (tid >> 5) + p * 8;
        sboff[p] = (A_ST_F + k * 128 + (((tid & 31) << 2) ^ ((k & 3) << 3))) * 4;
    }

    float acc[2][8][4];
    #pragma unroll
    for (int mb = 0; mb < 2; mb++)
        #pragma unroll
        for (int j = 0; j < 8; j++)
            #pragma unroll
            for (int v = 0; v < 4; v++) acc[mb][j][v] = 0.0f;

    // ---- load stage helper (macro-ish via lambda) ----
    auto load_stage = [&](int st, int kt) {
        uint32_t base = su + st * STAGE_BYTES;
        #pragma unroll
        for (int p = 0; p < 4; p++) {
            cp16(base + saoff[p], Ab + kt * 32 + p * 32 * 1024);
            cp16(base + sboff[p], Wb + (size_t)(kt * 32 + p * 8) * 1024);
        }
    };

    load_stage(0, 0);
    asm volatile("cp.async.commit_group;");
    load_stage(1, 1);
    asm volatile("cp.async.commit_group;");

    const int rowa0 = wm * 32 + qr;
    const int nbase = wn * 64 + qr;

    for (int kt = 0; kt < 32; kt++) {
        const int st = kt % 3;
        if (kt < 30) asm volatile("cp.async.wait_group 1;");
        else         asm volatile("cp.async.wait_group 0;");
        __syncthreads();
        if (kt < 30) {
            load_stage((kt + 2) % 3, kt + 2);
            asm volatile("cp.async.commit_group;");
        }

        const float* As = sm + st * STAGE_F;
        const float* Bs = As + A_ST_F;

        #pragma unroll
        for (int s = 0; s < 4; s++) {
            uint32_t afr[2][4];
            #pragma unroll
            for (int mb = 0; mb < 2; mb++) {
                int row = rowa0 + mb * 16;          // row&7 == qr
                int s0 = (((s * 2)     ^ qr) << 2) + qc;
                int s1 = (((s * 2 + 1) ^ qr) << 2) + qc;
                afr[mb][0] = f2tf32(As[row * 32 + s0]);
                afr[mb][1] = f2tf32(As[(row + 8) * 32 + s0]);
                afr[mb][2] = f2tf32(As[row * 32 + s1]);
                afr[mb][3] = f2tf32(As[(row + 8) * 32 + s1]);
            }
            uint32_t bfr[8][2];
            #pragma unroll
            for (int j = 0; j < 8; j++) {
                int nx = (nbase + j * 8) ^ (qc << 3);
                bfr[j][0] = f2tf32(Bs[(s * 8 + qc) * 128 + nx]);
                bfr[j][1] = f2tf32(Bs[(s * 8 + qc + 4) * 128 + nx]);
            }
            #pragma unroll
            for (int mb = 0; mb < 2; mb++)
                #pragma unroll
                for (int j = 0; j < 8; j++)
                    mma_tf32(acc[mb][j], afr[mb], bfr[j]);
        }
    }

    // epilogue
    #pragma unroll
    for (int mb = 0; mb < 2; mb++) {
        int row = bm * 128 + wm * 32 + mb * 16 + qr;
        #pragma unroll
        for (int j = 0; j < 8; j++) {
            int col = bn * 128 + wn * 64 + j * 8 + qc * 2;
            float2 bb = *(const float2*)(bias + col);
            float2 o0 = make_float2(acc[mb][j][0] + bb.x, acc[mb][j][1] + bb.y);
            float2 o1 = make_float2(acc[mb][j][2] + bb.x, acc[mb][j][3] + bb.y);
            *(float2*)(C + (size_t)row * 1024 + col)       = o0;
            *(float2*)(C + (size_t)(row + 8) * 1024 + col) = o1;
        }
    }
}

// ---------------- per-head means -------------------------------------------
__global__ __launch_bounds__(256) void means_kernel(
    const float* __restrict__ Qp, const float* __restrict__ Kp,
    float* __restrict__ qm, float* __restrict__ km)
{
    int warp = (blockIdx.x * blockDim.x + threadIdx.x) >> 5;
    int lane = threadIdx.x & 31;
    if (warp >= BH_ * L_) return;
    int bh = warp >> 12;
    int l  = warp & (L_ - 1);
    int b  = bh >> 4;
    int h  = bh & (H_ - 1);
    const float* qp = Qp + (size_t)(b * L_ + l) * D_ + h * DK_ + lane * 2;
    const float* kp = Kp + (size_t)(b * L_ + l) * D_ + h * DK_ + lane * 2;
    float2 q2 = *(const float2*)qp;
    float2 k2 = *(const float2*)kp;
    float qs = q2.x + q2.y;
    float ks = k2.x + k2.y;
    #pragma unroll
    for (int o = 16; o > 0; o >>= 1) {
        qs += __shfl_xor_sync(0xFFFFFFFFu, qs, o);
        ks += __shfl_xor_sync(0xFFFFFFFFu, ks, o);
    }
    if (lane == 0) {
        qm[warp] = qs * (1.0f / DK_);
        km[warp] = ks * (1.0f / DK_);
    }
}

// ---------------- circular cross-correlation -------------------------------
__global__ __launch_bounds__(256) void corr_kernel(
    const float* __restrict__ qm, const float* __restrict__ km,
    float* __restrict__ corr)
{
    __shared__ float sq[L_];
    __shared__ float sk[6144];

    const int bh = blockIdx.x;
    const int chunk = blockIdx.y;
    const int wb = (1 - chunk) * 2048;

    const float* q = qm + bh * L_;
    const float* k = km + bh * L_;
    for (int i = threadIdx.x; i < L_; i += 256) sq[i] = q[i];
    for (int i = threadIdx.x; i < 6144; i += 256) sk[i] = k[(i + wb) & (L_ - 1)];
    __syncthreads();

    const int t = threadIdx.x;
    float acc[8];
    #pragma unroll
    for (int j = 0; j < 8; j++) acc[j] = 0.0f;
    const float* kp = sk + 2048 - t;
    #pragma unroll 4
    for (int m = 0; m < L_; m++) {
        float qv = sq[m];
        #pragma unroll
        for (int j = 0; j < 8; j++)
            acc[j] += qv * kp[m - 256 * j];
    }
    #pragma unroll
    for (int j = 0; j < 8; j++)
        corr[bh * L_ + chunk * 2048 + t + 256 * j] = acc[j];
}

// ---------------- top-8 + softmax ------------------------------------------
__global__ __launch_bounds__(256) void top8_kernel(
    const float* __restrict__ corr, float* __restrict__ w, int* __restrict__ delays)
{
    __shared__ float sc[L_];
    __shared__ float svals[256];
    __shared__ int   sidx[256];
    __shared__ float topv[TOPK];
    __shared__ int   topi[TOPK];

    const int bh = blockIdx.x;
    for (int i = threadIdx.x; i < L_; i += 256) sc[i] = corr[bh * L_ + i];
    __syncthreads();

    for (int r = 0; r < TOPK; r++) {
        float best = -INFINITY; int bi = 0;
        for (int i = threadIdx.x; i < L_; i += 256) {
            float v = sc[i];
            if (v > best) { best = v; bi = i; }
        }
        svals[threadIdx.x] = best;
        sidx[threadIdx.x] = bi;
        __syncthreads();
        for (int s = 128; s > 0; s >>= 1) {
            if (threadIdx.x < s) {
                float v2 = svals[threadIdx.x + s];
                int   i2 = sidx[threadIdx.x + s];
                float v1 = svals[threadIdx.x];
                int   i1 = sidx[threadIdx.x];
                if (v2 > v1 || (v2 == v1 && i2 < i1)) {
                    svals[threadIdx.x] = v2;
                    sidx[threadIdx.x] = i2;
                }
            }
            __syncthreads();
        }
        if (threadIdx.x == 0) {
            topv[r] = svals[0];
            topi[r] = sidx[0];
            sc[sidx[0]] = -INFINITY;
        }
        __syncthreads();
    }

    if (threadIdx.x == 0) {
        float mx = topv[0];
        float e[TOPK], s = 0.0f;
        #pragma unroll
        for (int r = 0; r < TOPK; r++) { e[r] = expf(topv[r] - mx); s += e[r]; }
        float inv = 1.0f / s;
        #pragma unroll
        for (int r = 0; r < TOPK; r++) {
            w[bh * TOPK + r] = e[r] * inv;
            delays[bh * TOPK + r] = topi[r];
        }
    }
}

// ---------------- weighted circular-roll aggregation ----------------------
__global__ __launch_bounds__(256) void gather_kernel(
    const float* __restrict__ Vp, const float* __restrict__ w,
    const int* __restrict__ delays, float* __restrict__ out)
{
    unsigned gid = blockIdx.x * blockDim.x + threadIdx.x;  // one float4 each
    int d4 = gid & 255;
    int l  = (gid >> 8) & (L_ - 1);
    int b  = gid >> 20;
    int h  = d4 >> 4;
    int bh = b * H_ + h;

    float4 a = make_float4(0.f, 0.f, 0.f, 0.f);
    #pragma unroll
    for (int r = 0; r < TOPK; r++) {
        float wr = __ldg(&w[bh * TOPK + r]);
        int   dl = __ldg(&delays[bh * TOPK + r]);
        int   lm = (l - dl) & (L_ - 1);
        const float4 v = *(const float4*)(Vp + (size_t)(b * L_ + lm) * D_ + d4 * 4);
        a.x += wr * v.x; a.y += wr * v.y; a.z += wr * v.z; a.w += wr * v.w;
    }
    *(float4*)(out + (size_t)gid * 4) = a;
}

// ---------------- launch ---------------------------------------------------
extern "C" void kernel_launch(void* const* d_in, const int* in_sizes, int n_in,
                              void* d_out, int out_size)
{
    const float* queries = (const float*)d_in[0];
    const float* keys    = (const float*)d_in[1];
    const float* values  = (const float*)d_in[2];
    const float* Wq = (const float*)d_in[3];
    const float* bq = (const float*)d_in[4];
    const float* Wk = (const float*)d_in[5];
    const float* bk = (const float*)d_in[6];
    const float* Wv = (const float*)d_in[7];
    const float* bv = (const float*)d_in[8];
    const float* Wo = (const float*)d_in[9];
    const float* bo = (const float*)d_in[10];
    float* out = (float*)d_out;

    float *Qp, *Kp, *Vp, *pre, *qm, *km, *corr, *w;
    int* delays;
    cudaGetSymbolAddress((void**)&Qp, g_Qp);
    cudaGetSymbolAddress((void**)&Kp, g_Kp);
    cudaGetSymbolAddress((void**)&Vp, g_Vp);
    cudaGetSymbolAddress((void**)&pre, g_pre);
    cudaGetSymbolAddress((void**)&qm, g_qm);
    cudaGetSymbolAddress((void**)&km, g_km);
    cudaGetSymbolAddress((void**)&corr, g_corr);
    cudaGetSymbolAddress((void**)&w, g_w);
    cudaGetSymbolAddress((void**)&delays, g_delays);

    cudaFuncSetAttribute(gemm_tf32_kernel,
                         cudaFuncAttributeMaxDynamicSharedMemorySize, GEMM_SMEM);

    dim3 gemm_grid(8, 128);

    gemm_tf32_kernel<<<gemm_grid, 256, GEMM_SMEM>>>(queries, Wq, bq, Qp);
    gemm_tf32_kernel<<<gemm_grid, 256, GEMM_SMEM>>>(keys,    Wk, bk, Kp);
    gemm_tf32_kernel<<<gemm_grid, 256, GEMM_SMEM>>>(values,  Wv, bv, Vp);

    means_kernel<<<(BH_ * L_ * 32) / 256, 256>>>(Qp, Kp, qm, km);

    dim3 corr_grid(BH_, 2);
    corr_kernel<<<corr_grid, 256>>>(qm, km, corr);

    top8_kernel<<<BH_, 256>>>(corr, w, delays);

    gather_kernel<<<(M_ * D_ / 4) / 256, 256>>>(Vp, w, delays, pre);

    gemm_tf32_kernel<<<gemm_grid, 256, GEMM_SMEM>>>(pre, Wo, bo, out);
}